// round 5
// baseline (speedup 1.0000x reference)
#include <cuda_runtime.h>
#include <cuda_bf16.h>
#include <math.h>

#define BZ 32
#define SZ 128
#define HZ 768
#define MM 8
#define MH_ 6
#define KK 4

__constant__ float c_inv[8] = {1.f, 1.f/2.f, 1.f/3.f, 1.f/4.f, 1.f/5.f, 1.f/6.f, 1.f/7.f, 1.f/8.f};

#define CE(x, y) { unsigned long long _a = (x), _b = (y); (x) = _a > _b ? _a : _b; (y) = _a > _b ? _b : _a; }

// out layout (floats): implicit[0,512) explicit[512,2560) hs[2560,35328) ts[35328,68096)

__global__ __launch_bounds__(1024, 1) void k_fused(
    const float* __restrict__ emb,
    const int* __restrict__ mask,
    const float* __restrict__ wh,
    const float* __restrict__ bh_,
    const float* __restrict__ wt,
    const float* __restrict__ bt_,
    const float* __restrict__ wi,
    const float* __restrict__ bi,
    const float* __restrict__ we,
    const float* __restrict__ be,
    float* __restrict__ out)
{
    // buf: phase 0 = weight cache (wh:[0,192) f4, wt:[192,384) f4)
    //      phase 3+ = scores sc[2][1024]
    __shared__ __align__(16) float buf[2048];        // 8 KB
    __shared__ __align__(16) float swi[HZ * 4];      // 12 KB
    __shared__ __align__(16) float swe[2 * HZ * 4];  // 24 KB
    __shared__ float pref[2][SZ + 1];                // [0]=target(wt), [1]=holder(wh)
    __shared__ unsigned long long cand[2][64];
    __shared__ float topv[2][KK];
    __shared__ int   topi[2][KK];
    __shared__ float partial[24][8];
    __shared__ float sbias[10];                      // 0:bh 1:bt 2-5:bi 6-9:be
    __shared__ int s_len;

    const int b = blockIdx.x;
    const int tid = threadIdx.x;
    const int warp = tid >> 5, lane = tid & 31;
    const float* eb = emb + (size_t)b * SZ * HZ;

    // ---- prefetch ALL weights into smem in one burst (one DRAM latency) ----
    {
        float4* buf4 = (float4*)buf;
        float4* swi4 = (float4*)swi;
        float4* swe4 = (float4*)swe;
        const float4* wh4 = (const float4*)wh;
        const float4* wt4 = (const float4*)wt;
        const float4* wi4 = (const float4*)wi;
        const float4* we4 = (const float4*)we;
#pragma unroll
        for (int i = 0; i < 3; i++) {
            int j = tid + 1024 * i;
            if (j < 192)        buf4[j] = wh4[j];
            else if (j < 384)   buf4[j] = wt4[j - 192];
            else if (j < 1152)  swi4[j - 384] = wi4[j - 384];
            else if (j < 2688)  swe4[j - 1152] = we4[j - 1152];
        }
        if (tid == 0) { sbias[0] = bh_[0]; sbias[1] = bt_[0]; s_len = 0; }
        else if (tid >= 2 && tid < 6)  sbias[tid] = bi[tid - 2];
        else if (tid >= 6 && tid < 10) sbias[tid] = be[tid - 6];
        if (tid < 2) { pref[tid][0] = 0.f; }
    }
    // mask length (warps 0-3)
    if (tid < SZ) {
        int v = mask[b * SZ + tid];
#pragma unroll
        for (int off = 16; off; off >>= 1) v += __shfl_xor_sync(0xFFFFFFFFu, v, off);
        if (lane == 0) atomicAdd(&s_len, v);
    }
    __syncthreads();

    // ---- phase 0: per-row wh/wt dots, 4 rows per warp, weights from smem ----
    {
        const float4* buf4 = (const float4*)buf;
#pragma unroll 1
        for (int r = warp * 4; r < warp * 4 + 4; r++) {
            const float4* rp = (const float4*)(eb + (size_t)r * HZ);
            float4 v[6];
#pragma unroll
            for (int i = 0; i < 6; i++) v[i] = rp[lane + 32 * i];
            float ah = 0.f, at = 0.f;
#pragma unroll
            for (int i = 0; i < 6; i++) {
                float4 wv = buf4[lane + 32 * i];
                float4 tv = buf4[192 + lane + 32 * i];
                ah += v[i].x * wv.x + v[i].y * wv.y + v[i].z * wv.z + v[i].w * wv.w;
                at += v[i].x * tv.x + v[i].y * tv.y + v[i].z * tv.z + v[i].w * tv.w;
            }
#pragma unroll
            for (int off = 16; off; off >>= 1) {
                ah += __shfl_xor_sync(0xFFFFFFFFu, ah, off);
                at += __shfl_xor_sync(0xFFFFFFFFu, at, off);
            }
            if (lane == 0) {
                pref[0][r + 1] = at;
                pref[1][r + 1] = ah;
            }
        }
    }
    __syncthreads();

    // ---- phase 2: prefix sums over S (warps 0,1) ----
    if (warp < 2) {
        const int c = warp;
        float v0 = pref[c][lane * 4 + 1];
        float v1 = pref[c][lane * 4 + 2];
        float v2 = pref[c][lane * 4 + 3];
        float v3 = pref[c][lane * 4 + 4];
        v1 += v0; v2 += v1; v3 += v2;
        float tot = v3, x = tot;
#pragma unroll
        for (int off = 1; off < 32; off <<= 1) {
            float y = __shfl_up_sync(0xFFFFFFFFu, x, off);
            if (lane >= off) x += y;
        }
        float excl = x - tot;
        pref[c][lane * 4 + 1] = v0 + excl;
        pref[c][lane * 4 + 2] = v1 + excl;
        pref[c][lane * 4 + 3] = v2 + excl;
        pref[c][lane * 4 + 4] = v3 + excl;
    }
    __syncthreads();

    // ---- phase 3: span scores (1 per thread) + hs/ts outputs ----
    {
        const int len = s_len;
        const float bhv = sbias[0], btv = sbias[1];
        int idx = tid;
        int m = idx >> 7, s = idx & 127;
        int e = s + m + 1; if (e > SZ) e = SZ;
        float invw = c_inv[m];
        bool tv = (s + m) < len;
        bool hv = tv && (m < MH_);
        float dt = (pref[0][e] - pref[0][s]) * invw;
        float dh = (pref[1][e] - pref[1][s]) * invw;
        float vt = tv ? 1.f / (1.f + __expf(-(dt + btv))) : -1.f;
        float vh = hv ? 1.f / (1.f + __expf(-(dh + bhv))) : -1.f;
        buf[idx] = vt;            // sc[0] = ts
        buf[1024 + idx] = vh;     // sc[1] = hs
        out[35328 + (size_t)b * (MM * SZ) + idx] = vt;
        out[2560  + (size_t)b * (MM * SZ) + idx] = vh;
    }
    __syncthreads();

    // ---- phase 4: top-4 (t: warps 0-15, h: warps 16-31) ----
    {
        const int type = warp >> 4;
        const int base = tid & 511;
        unsigned long long k0, k1, k2 = 0ull, k3 = 0ull;
        {
            unsigned u0 = __float_as_uint(buf[type * 1024 + base]);
            unsigned u1 = __float_as_uint(buf[type * 1024 + base + 512]);
            u0 = (u0 & 0x80000000u) ? ~u0 : (u0 | 0x80000000u);
            u1 = (u1 & 0x80000000u) ? ~u1 : (u1 | 0x80000000u);
            k0 = ((unsigned long long)u0 << 32) | (unsigned)(0xFFFFFFFFu - base);
            k1 = ((unsigned long long)u1 << 32) | (unsigned)(0xFFFFFFFFu - (base + 512));
            CE(k0, k1);
        }
#pragma unroll
        for (int off = 16; off; off >>= 1) {
            unsigned long long o0 = __shfl_xor_sync(0xFFFFFFFFu, k0, off);
            unsigned long long o1 = __shfl_xor_sync(0xFFFFFFFFu, k1, off);
            unsigned long long o2 = __shfl_xor_sync(0xFFFFFFFFu, k2, off);
            unsigned long long o3 = __shfl_xor_sync(0xFFFFFFFFu, k3, off);
            unsigned long long c0 = k0 > o3 ? k0 : o3;
            unsigned long long c1 = k1 > o2 ? k1 : o2;
            unsigned long long c2 = k2 > o1 ? k2 : o1;
            unsigned long long c3 = k3 > o0 ? k3 : o0;
            CE(c0, c2); CE(c1, c3);
            CE(c0, c1); CE(c2, c3);
            k0 = c0; k1 = c1; k2 = c2; k3 = c3;
        }
        if (lane == 0) {
            int wq = warp & 15;
            cand[type][wq * 4 + 0] = k0;
            cand[type][wq * 4 + 1] = k1;
            cand[type][wq * 4 + 2] = k2;
            cand[type][wq * 4 + 3] = k3;
        }
    }
    __syncthreads();

    // ---- final selection over 64 candidates (warps 0 and 16) ----
    if (warp == 0 || warp == 16) {
        const int type = warp >> 4;
        unsigned long long key0 = cand[type][lane];
        unsigned long long key1 = cand[type][lane + 32];
#pragma unroll
        for (int k = 0; k < KK; k++) {
            unsigned long long loc = key0 > key1 ? key0 : key1;
            unsigned long long red = loc;
#pragma unroll
            for (int off = 16; off; off >>= 1) {
                unsigned long long o = __shfl_xor_sync(0xFFFFFFFFu, red, off);
                red = o > red ? o : red;
            }
            if (key0 == red) key0 = 0ull;
            else if (key1 == red) key1 = 0ull;
            if (lane == 0) {
                unsigned hi = (unsigned)(red >> 32);
                unsigned lo = (unsigned)red;
                float v = (hi & 0x80000000u) ? __uint_as_float(hi ^ 0x80000000u)
                                             : __uint_as_float(~hi);
                topv[type][k] = v;
                topi[type][k] = (int)(0xFFFFFFFFu - lo);
            }
        }
    }
    __syncthreads();

    // ---- phase 5: rep dots, 3 warps per span (warps 0-23) ----
    if (warp < 24) {
        const int type = warp / 12;          // 0 = target, 1 = holder
        const int w2 = warp % 12;
        const int span = w2 / 3;
        const int seg = w2 % 3;
        const int idx = topi[type][span];
        const bool valid = topv[type][span] > 0.f;
        const int m = idx >> 7, s = idx & 127;
        const float invw = c_inv[m];
        const int c0 = lane + 64 * seg;      // two float4 columns per lane
        const int c1 = c0 + 32;

        float4 s0 = make_float4(0.f,0.f,0.f,0.f), s1 = s0;
        if (valid) {
#pragma unroll
            for (int ch = 0; ch < 2; ch++) {
                float4 a[4], bb[4];
#pragma unroll
                for (int r4 = 0; r4 < 4; r4++) {
                    int r = ch * 4 + r4;
                    if (r <= m) {
                        const float4* rp = (const float4*)(eb + (size_t)(s + r) * HZ);
                        a[r4] = rp[c0]; bb[r4] = rp[c1];
                    } else {
                        a[r4] = make_float4(0.f,0.f,0.f,0.f);
                        bb[r4] = a[r4];
                    }
                }
#pragma unroll
                for (int r4 = 0; r4 < 4; r4++) {
                    s0.x += a[r4].x;  s0.y += a[r4].y;  s0.z += a[r4].z;  s0.w += a[r4].w;
                    s1.x += bb[r4].x; s1.y += bb[r4].y; s1.z += bb[r4].z; s1.w += bb[r4].w;
                }
            }
        }
        float acc[8] = {0.f,0.f,0.f,0.f,0.f,0.f,0.f,0.f};
        if (valid) {
            const float4* swi4 = (const float4*)swi;
            const float4* swe4 = (const float4*)swe;
            float4 sums[2] = {s0, s1};
            int cols[2] = {c0, c1};
#pragma unroll
            for (int cc = 0; cc < 2; cc++) {
                float sv[4] = {sums[cc].x * invw, sums[cc].y * invw,
                               sums[cc].z * invw, sums[cc].w * invw};
#pragma unroll
                for (int j = 0; j < 4; j++) {
                    int f = 4 * cols[cc] + j;
                    if (type == 0) {
                        float4 wv = swi4[f];
                        acc[0] += sv[j] * wv.x; acc[1] += sv[j] * wv.y;
                        acc[2] += sv[j] * wv.z; acc[3] += sv[j] * wv.w;
                        float4 ev = swe4[HZ + f];
                        acc[4] += sv[j] * ev.x; acc[5] += sv[j] * ev.y;
                        acc[6] += sv[j] * ev.z; acc[7] += sv[j] * ev.w;
                    } else {
                        float4 ev = swe4[f];
                        acc[0] += sv[j] * ev.x; acc[1] += sv[j] * ev.y;
                        acc[2] += sv[j] * ev.z; acc[3] += sv[j] * ev.w;
                    }
                }
            }
        }
        const int nred = (type == 0) ? 8 : 4;
        for (int j = 0; j < nred; j++)
#pragma unroll
            for (int off = 16; off; off >>= 1)
                acc[j] += __shfl_xor_sync(0xFFFFFFFFu, acc[j], off);
        if (lane == 0) {
#pragma unroll
            for (int j = 0; j < 8; j++) partial[warp][j] = acc[j];
        }
    }
    __syncthreads();

    // ---- phase 6: logits ----
    if (tid < 64) {
        int k = tid >> 4, i = (tid >> 2) & 3, j = tid & 3;
        bool pv = (topv[1][k] > 0.f) && (topv[0][i] > 0.f);
        float val = sbias[6 + j];
        if (pv) {
#pragma unroll
            for (int sgi = 0; sgi < 3; sgi++)
                val += partial[12 + 3*k + sgi][j] + partial[3*i + sgi][4 + j];
        }
        out[512 + (size_t)b * 64 + tid] = val;
    } else if (tid < 80) {
        int t2 = tid - 64;
        int i = t2 >> 2, j = t2 & 3;
        float val = sbias[2 + j];
        if (topv[0][i] > 0.f) {
#pragma unroll
            for (int sgi = 0; sgi < 3; sgi++)
                val += partial[3*i + sgi][j];
        }
        out[(size_t)b * 16 + t2] = val;
    }
}

extern "C" void kernel_launch(void* const* d_in, const int* in_sizes, int n_in,
                              void* d_out, int out_size)
{
    const float* emb = (const float*)d_in[0];
    const int*   msk = (const int*)d_in[1];
    const float* wh  = (const float*)d_in[2];
    const float* bh  = (const float*)d_in[3];
    const float* wt  = (const float*)d_in[4];
    const float* bt  = (const float*)d_in[5];
    const float* wi  = (const float*)d_in[6];
    const float* bi  = (const float*)d_in[7];
    const float* we  = (const float*)d_in[8];
    const float* be  = (const float*)d_in[9];
    float* out = (float*)d_out;

    k_fused<<<BZ, 1024>>>(emb, msk, wh, bh, wt, bt, wi, bi, we, be, out);
}